// round 2
// baseline (speedup 1.0000x reference)
#include <cuda_runtime.h>
#include <cuda_bf16.h>

#define T_STEPS 512
#define HID 64
#define PAD 68            // row stride for W tiles: j*17 float4s -> conflict-free octets
#define NB  8             // batches per block
#define R   4             // batches per thread

// dynamic smem layout (floats):
//   w0  : [64][PAD]  W_hh0[j][k]
//   w1h : [64][PAD]  W_hh1[j][k]
//   w1i : [64][PAD]  W_ih1[j][k]
//   h0  : [2][NB][64] double buffer
//   h1  : [NB][64]
#define SMEM_FLOATS (3*64*PAD + 2*NB*64 + NB*64)

__global__ __launch_bounds__(128)
void rnn_fused_kernel(const float* __restrict__ x,
                      const float* __restrict__ Wih0,
                      const float* __restrict__ Whh0,
                      const float* __restrict__ bih0,
                      const float* __restrict__ bhh0,
                      const float* __restrict__ Wih1,
                      const float* __restrict__ Whh1,
                      const float* __restrict__ bih1,
                      const float* __restrict__ bhh1,
                      const float* __restrict__ fcw,
                      const float* __restrict__ fcb,
                      float* __restrict__ out)
{
    extern __shared__ float sm[];
    float* w0   = sm;                    // 64*PAD
    float* w1h  = w0  + 64 * PAD;
    float* w1i  = w1h + 64 * PAD;
    float* h0b  = w1i + 64 * PAD;        // [2][NB][64]
    float* h1   = h0b + 2 * NB * 64;     // [NB][64]

    const int tid = threadIdx.x;
    const int j   = tid & 63;            // output unit
    const int g   = tid >> 6;            // batch group 0/1
    const int bblk = blockIdx.x * NB;    // first batch of this block

    // stage the three 64x64 weight matrices into padded smem
    for (int idx = tid; idx < 64 * 64; idx += 128) {
        int r = idx >> 6, c = idx & 63;
        w0 [r * PAD + c] = Whh0[idx];
        w1h[r * PAD + c] = Whh1[idx];
        w1i[r * PAD + c] = Wih1[idx];
    }
    // zero states
    for (int idx = tid; idx < 2 * NB * 64; idx += 128) h0b[idx] = 0.0f;
    for (int idx = tid; idx < NB * 64;     idx += 128) h1[idx]  = 0.0f;

    // per-thread register-resident input weights + fused biases
    float wih0r[8];
#pragma unroll
    for (int i = 0; i < 8; ++i) wih0r[i] = Wih0[j * 8 + i];
    const float bias0 = bih0[j] + bhh0[j];
    const float bias1 = bih1[j] + bhh1[j];

    // x row base pointers for this thread's R batches
    const float* xp[R];
#pragma unroll
    for (int r = 0; r < R; ++r)
        xp[r] = x + (size_t)(bblk + g * R + r) * (T_STEPS * 8);

    __syncthreads();

    int cur = 0;
    for (int t = 0; t < T_STEPS; ++t) {
        float* h0c = h0b + cur * (NB * 64);
        float* h0n = h0b + (cur ^ 1) * (NB * 64);

        // issue x loads early; consumed after the k-loop (latency hidden)
        float4 xa[R], xb4[R];
#pragma unroll
        for (int r = 0; r < R; ++r) {
            xa[r]  = *reinterpret_cast<const float4*>(xp[r] + t * 8);
            xb4[r] = *reinterpret_cast<const float4*>(xp[r] + t * 8 + 4);
        }

        float acc0[R], acc1[R];
#pragma unroll
        for (int r = 0; r < R; ++r) { acc0[r] = 0.0f; acc1[r] = bias1; }

        // phase A: h0_old @ Whh0^T and h1_old @ Whh1^T
#pragma unroll
        for (int k4 = 0; k4 < 16; ++k4) {
            const float4 wv0 = *reinterpret_cast<const float4*>(&w0 [j * PAD + k4 * 4]);
            const float4 wv1 = *reinterpret_cast<const float4*>(&w1h[j * PAD + k4 * 4]);
#pragma unroll
            for (int r = 0; r < R; ++r) {
                const int bl = g * R + r;
                const float4 h0v = *reinterpret_cast<const float4*>(&h0c[bl * 64 + k4 * 4]);
                const float4 h1v = *reinterpret_cast<const float4*>(&h1 [bl * 64 + k4 * 4]);
                acc0[r] += h0v.x * wv0.x + h0v.y * wv0.y + h0v.z * wv0.z + h0v.w * wv0.w;
                acc1[r] += h1v.x * wv1.x + h1v.y * wv1.y + h1v.z * wv1.z + h1v.w * wv1.w;
            }
        }

        float h0new[R];
#pragma unroll
        for (int r = 0; r < R; ++r) {
            float s = acc0[r] + bias0;
            s += xa[r].x  * wih0r[0] + xa[r].y  * wih0r[1]
               + xa[r].z  * wih0r[2] + xa[r].w  * wih0r[3]
               + xb4[r].x * wih0r[4] + xb4[r].y * wih0r[5]
               + xb4[r].z * wih0r[6] + xb4[r].w * wih0r[7];
            h0new[r] = tanhf(s);
        }

        // publish new h0 to the OTHER buffer (no read-write conflict)
#pragma unroll
        for (int r = 0; r < R; ++r)
            h0n[(g * R + r) * 64 + j] = h0new[r];

        __syncthreads();   // all old-state reads done + h0new visible

        // phase B: h0_new @ Wih1^T
#pragma unroll
        for (int k4 = 0; k4 < 16; ++k4) {
            const float4 wv = *reinterpret_cast<const float4*>(&w1i[j * PAD + k4 * 4]);
#pragma unroll
            for (int r = 0; r < R; ++r) {
                const int bl = g * R + r;
                const float4 hv = *reinterpret_cast<const float4*>(&h0n[bl * 64 + k4 * 4]);
                acc1[r] += hv.x * wv.x + hv.y * wv.y + hv.z * wv.z + hv.w * wv.w;
            }
        }
#pragma unroll
        for (int r = 0; r < R; ++r)
            h1[(g * R + r) * 64 + j] = tanhf(acc1[r]);

        __syncthreads();   // h1 writes visible for next step's phase A
        cur ^= 1;
    }

    // final FC on last h1: out[b] = h1[b]·fcw + fcb
    if (tid < NB) {
        float s = 0.0f;
        const float* hrow = h1 + tid * 64;
#pragma unroll 16
        for (int k = 0; k < 64; ++k) s += hrow[k] * fcw[k];
        out[bblk + tid] = s + fcb[0];
    }
}

extern "C" void kernel_launch(void* const* d_in, const int* in_sizes, int n_in,
                              void* d_out, int out_size)
{
    const float* x    = (const float*)d_in[0];
    const float* Wih0 = (const float*)d_in[1];
    const float* Whh0 = (const float*)d_in[2];
    const float* bih0 = (const float*)d_in[3];
    const float* bhh0 = (const float*)d_in[4];
    const float* Wih1 = (const float*)d_in[5];
    const float* Whh1 = (const float*)d_in[6];
    const float* bih1 = (const float*)d_in[7];
    const float* bhh1 = (const float*)d_in[8];
    const float* fcw  = (const float*)d_in[9];
    const float* fcb  = (const float*)d_in[10];
    float* out = (float*)d_out;

    const size_t smem = SMEM_FLOATS * sizeof(float);   // 58368 B > 48KB static limit
    cudaFuncSetAttribute(rnn_fused_kernel,
                         cudaFuncAttributeMaxDynamicSharedMemorySize, (int)smem);

    rnn_fused_kernel<<<2048 / NB, 128, smem>>>(
        x, Wih0, Whh0, bih0, bhh0, Wih1, Whh1, bih1, bhh1, fcw, fcb, out);
}

// round 4
// speedup vs baseline: 1.5702x; 1.5702x over previous
#include <cuda_runtime.h>
#include <cuda_bf16.h>

#define T_STEPS 512
#define NB 7                       // batches per block
#define NBLK ((2048 + NB - 1) / NB)  // 293 blocks
#define NTHREADS 192               // 3 groups x 64 j

typedef unsigned long long ull;

__device__ __forceinline__ ull ffma2(ull a, ull b, ull c) {
    ull d;
    asm("fma.rn.f32x2 %0, %1, %2, %3;" : "=l"(d) : "l"(a), "l"(b), "l"(c));
    return d;
}
__device__ __forceinline__ float hsum2(ull v) {
    float lo, hi;
    asm("mov.b64 {%0, %1}, %2;" : "=f"(lo), "=f"(hi) : "l"(v));
    return lo + hi;
}

__global__ __launch_bounds__(NTHREADS, 2)
void rnn_ws_kernel(const float* __restrict__ x,
                   const float* __restrict__ Wih0,
                   const float* __restrict__ Whh0,
                   const float* __restrict__ bih0,
                   const float* __restrict__ bhh0,
                   const float* __restrict__ Wih1,
                   const float* __restrict__ Whh1,
                   const float* __restrict__ bih1,
                   const float* __restrict__ bhh1,
                   const float* __restrict__ fcw,
                   const float* __restrict__ fcb,
                   float* __restrict__ out)
{
    // h state: double-buffered, read with warp-uniform (broadcast) addresses only
    __shared__ float h0buf[2][NB][64];
    __shared__ float h1buf[2][NB][64];
    __shared__ float cbuf[NB][64];          // W_ih1 . h0new partial

    const int tid = threadIdx.x;
    const int j   = tid & 63;               // output unit
    const int g   = tid >> 6;               // 0: layer0, 1: W_ih1 part, 2: W_hh1 part + combine
    const int b0  = blockIdx.x * NB;

    // ---- load this thread's W row into registers, packed as f32x2 pairs ----
    const float* wsrc = (g == 0) ? (Whh0 + j * 64)
                      : (g == 1) ? (Wih1 + j * 64)
                                 : (Whh1 + j * 64);
    ull w[32];
#pragma unroll
    for (int i = 0; i < 16; ++i) {
        ulonglong2 v = *reinterpret_cast<const ulonglong2*>(wsrc + i * 4);
        w[2 * i] = v.x; w[2 * i + 1] = v.y;
    }

    // group-specific extras
    ull wx[4] = {0, 0, 0, 0};
    float bias0 = 0.f, bias1 = 0.f;
    const float* xptr[NB];
    if (g == 0) {
        ulonglong2 v0 = *reinterpret_cast<const ulonglong2*>(Wih0 + j * 8);
        ulonglong2 v1 = *reinterpret_cast<const ulonglong2*>(Wih0 + j * 8 + 4);
        wx[0] = v0.x; wx[1] = v0.y; wx[2] = v1.x; wx[3] = v1.y;
        bias0 = bih0[j] + bhh0[j];
#pragma unroll
        for (int b = 0; b < NB; ++b) {
            int bb = b0 + b;
            xptr[b] = x + (size_t)(bb < 2048 ? bb : 0) * (T_STEPS * 8);
        }
    }
    if (g == 2) bias1 = bih1[j] + bhh1[j];

    // zero the initial-state buffers (buffer 0 of each)
    for (int idx = tid; idx < NB * 64; idx += NTHREADS) {
        (&h0buf[0][0][0])[idx] = 0.0f;
        (&h1buf[0][0][0])[idx] = 0.0f;
    }
    __syncthreads();

    int p = 0;   // h0 read-buffer parity
    int q = 0;   // h1 read-buffer parity

    // slot it: G0 computes h0(it);  G1/G2 compute h1(it-1)  (one-step software pipeline)
    for (int it = 0; it <= T_STEPS; ++it) {
        float pacc[NB];                      // G2's W_hh1 partial, carried across barrier

        if (g == 0) {
            if (it < T_STEPS) {
                // prefetch x(it) for all batches (consumed after the k-loop)
                ull xa[NB][4];
#pragma unroll
                for (int b = 0; b < NB; ++b) {
                    ulonglong2 v0 = *reinterpret_cast<const ulonglong2*>(xptr[b] + it * 8);
                    ulonglong2 v1 = *reinterpret_cast<const ulonglong2*>(xptr[b] + it * 8 + 4);
                    xa[b][0] = v0.x; xa[b][1] = v0.y; xa[b][2] = v1.x; xa[b][3] = v1.y;
                }
                ull acc[NB];
#pragma unroll
                for (int b = 0; b < NB; ++b) acc[b] = 0ull;
                const float* hrow = &h0buf[p][0][0];
#pragma unroll
                for (int i = 0; i < 16; ++i) {
                    const ull w0 = w[2 * i], w1 = w[2 * i + 1];
#pragma unroll
                    for (int b = 0; b < NB; ++b) {
                        ulonglong2 hv = *reinterpret_cast<const ulonglong2*>(hrow + b * 64 + i * 4);
                        acc[b] = ffma2(w0, hv.x, acc[b]);
                        acc[b] = ffma2(w1, hv.y, acc[b]);
                    }
                }
#pragma unroll
                for (int b = 0; b < NB; ++b) {
                    acc[b] = ffma2(wx[0], xa[b][0], acc[b]);
                    acc[b] = ffma2(wx[1], xa[b][1], acc[b]);
                    acc[b] = ffma2(wx[2], xa[b][2], acc[b]);
                    acc[b] = ffma2(wx[3], xa[b][3], acc[b]);
                    h0buf[p ^ 1][b][j] = tanhf(hsum2(acc[b]) + bias0);
                }
            }
        } else if (g == 1) {
            if (it >= 1) {
                // c(it-1) = W_ih1 . h0(it-1)   (h0buf[p] holds h0(it-1))
                ull acc[NB];
#pragma unroll
                for (int b = 0; b < NB; ++b) acc[b] = 0ull;
                const float* hrow = &h0buf[p][0][0];
#pragma unroll
                for (int i = 0; i < 16; ++i) {
                    const ull w0 = w[2 * i], w1 = w[2 * i + 1];
#pragma unroll
                    for (int b = 0; b < NB; ++b) {
                        ulonglong2 hv = *reinterpret_cast<const ulonglong2*>(hrow + b * 64 + i * 4);
                        acc[b] = ffma2(w0, hv.x, acc[b]);
                        acc[b] = ffma2(w1, hv.y, acc[b]);
                    }
                }
#pragma unroll
                for (int b = 0; b < NB; ++b) cbuf[b][j] = hsum2(acc[b]);
            }
        } else {
            if (it >= 1) {
                // p(it-1) = W_hh1 . h1(it-2)   (h1buf[q] holds h1(it-2))
                ull acc[NB];
#pragma unroll
                for (int b = 0; b < NB; ++b) acc[b] = 0ull;
                const float* hrow = &h1buf[q][0][0];
#pragma unroll
                for (int i = 0; i < 16; ++i) {
                    const ull w0 = w[2 * i], w1 = w[2 * i + 1];
#pragma unroll
                    for (int b = 0; b < NB; ++b) {
                        ulonglong2 hv = *reinterpret_cast<const ulonglong2*>(hrow + b * 64 + i * 4);
                        acc[b] = ffma2(w0, hv.x, acc[b]);
                        acc[b] = ffma2(w1, hv.y, acc[b]);
                    }
                }
#pragma unroll
                for (int b = 0; b < NB; ++b) pacc[b] = hsum2(acc[b]);
            }
        }

        __syncthreads();   // h0new + cbuf published

        if (g == 2 && it >= 1) {
            // combine: h1(it-1) = tanh(W_ih1 h0 + W_hh1 h1 + biases)
#pragma unroll
            for (int b = 0; b < NB; ++b)
                h1buf[q ^ 1][b][j] = tanhf(pacc[b] + cbuf[b][j] + bias1);
        }

        __syncthreads();   // h1 published for next slot

        if (it < T_STEPS) p ^= 1;
        if (it >= 1)      q ^= 1;
    }

    // final FC on h1(T-1): q is back to the buffer holding the last state
    if (tid < NB && b0 + tid < 2048) {
        float s = fcb[0];
        const float* hrow = &h1buf[q][tid][0];
#pragma unroll 16
        for (int k = 0; k < 64; ++k) s += hrow[k] * fcw[k];
        out[b0 + tid] = s;
    }
}

extern "C" void kernel_launch(void* const* d_in, const int* in_sizes, int n_in,
                              void* d_out, int out_size)
{
    const float* x    = (const float*)d_in[0];
    const float* Wih0 = (const float*)d_in[1];
    const float* Whh0 = (const float*)d_in[2];
    const float* bih0 = (const float*)d_in[3];
    const float* bhh0 = (const float*)d_in[4];
    const float* Wih1 = (const float*)d_in[5];
    const float* Whh1 = (const float*)d_in[6];
    const float* bih1 = (const float*)d_in[7];
    const float* bhh1 = (const float*)d_in[8];
    const float* fcw  = (const float*)d_in[9];
    const float* fcb  = (const float*)d_in[10];
    float* out = (float*)d_out;

    rnn_ws_kernel<<<NBLK, NTHREADS>>>(
        x, Wih0, Whh0, bih0, bhh0, Wih1, Whh1, bih1, bhh1, fcw, fcb, out);
}

// round 6
// speedup vs baseline: 1.8124x; 1.1542x over previous
#include <cuda_runtime.h>
#include <cuda_bf16.h>

#define T_STEPS 512
#define NB 7                         // batches per block
#define NBLK ((2048 + NB - 1) / NB)  // 293 blocks -> one wave at 2 CTA/SM
#define NTHREADS 192                 // 3 groups x 64 j

typedef unsigned long long ull;

__device__ __forceinline__ ull ffma2(ull a, ull b, ull c) {
    ull d;
    asm("fma.rn.f32x2 %0, %1, %2, %3;" : "=l"(d) : "l"(a), "l"(b), "l"(c));
    return d;
}
__device__ __forceinline__ float hsum2(ull v) {
    float lo, hi;
    asm("mov.b64 {%0, %1}, %2;" : "=f"(lo), "=f"(hi) : "l"(v));
    return lo + hi;
}
__device__ __forceinline__ ull pack2(float lo, float hi) {
    ull d;
    asm("mov.b64 %0, {%1, %2};" : "=l"(d) : "f"(lo), "f"(hi));
    return d;
}
// branch-free tanh: 1 - 2/(exp(2s)+1), ex2/rcp approx (abs err ~1e-7)
__device__ __forceinline__ float tanh_fast(float s) {
    float e;
    asm("ex2.approx.f32 %0, %1;" : "=f"(e) : "f"(s * 2.8853900817779268f));
    float r;
    asm("rcp.approx.f32 %0, %1;" : "=f"(r) : "f"(e + 1.0f));
    return __fmaf_rn(-2.0f, r, 1.0f);
}

__global__ __launch_bounds__(NTHREADS, 2)
void rnn_ws_kernel(const float* __restrict__ x,
                   const float* __restrict__ Wih0,
                   const float* __restrict__ Whh0,
                   const float* __restrict__ bih0,
                   const float* __restrict__ bhh0,
                   const float* __restrict__ Wih1,
                   const float* __restrict__ Whh1,
                   const float* __restrict__ bih1,
                   const float* __restrict__ bhh1,
                   const float* __restrict__ fcw,
                   const float* __restrict__ fcb,
                   float* __restrict__ out)
{
    __shared__ __align__(16) float h0buf[2][NB][64];
    __shared__ __align__(16) float h1buf[2][NB][64];
    __shared__ __align__(16) float cbuf[2][NB][64];   // double-buffered W_ih1.h0 partial
    __shared__ __align__(16) float xbuf[2][NB][8];    // double-buffered x slice

    const int tid = threadIdx.x;
    const int j   = tid & 63;          // output unit
    const int g   = tid >> 6;          // 0: layer0, 1: W_ih1 + x prefetch, 2: W_hh1 + combine
    const int b0  = blockIdx.x * NB;

    // this thread's 64-float W row, packed f32x2 in registers
    const float* wsrc = (g == 0) ? (Whh0 + j * 64)
                      : (g == 1) ? (Wih1 + j * 64)
                                 : (Whh1 + j * 64);
    ull w[32];
#pragma unroll
    for (int i = 0; i < 16; ++i) {
        ulonglong2 v = *reinterpret_cast<const ulonglong2*>(wsrc + i * 4);
        w[2 * i] = v.x; w[2 * i + 1] = v.y;
    }

    ull wx[4] = {0, 0, 0, 0};
    float bias0 = 0.f, bias1 = 0.f;
    if (g == 0) {
        ulonglong2 v0 = *reinterpret_cast<const ulonglong2*>(Wih0 + j * 8);
        ulonglong2 v1 = *reinterpret_cast<const ulonglong2*>(Wih0 + j * 8 + 4);
        wx[0] = v0.x; wx[1] = v0.y; wx[2] = v1.x; wx[3] = v1.y;
        bias0 = bih0[j] + bhh0[j];
    }
    if (g == 2) bias1 = bih1[j] + bhh1[j];

    // zero initial states
    for (int idx = tid; idx < NB * 64; idx += NTHREADS) {
        (&h0buf[0][0][0])[idx] = 0.0f;
        (&h1buf[0][0][0])[idx] = 0.0f;
    }
    // preload x(0) into xbuf[0]
    if (tid < 2 * NB) {
        int b = tid >> 1, half = tid & 1;
        int bb = b0 + b; if (bb > 2047) bb = 2047;
        float4 v = *reinterpret_cast<const float4*>(x + (size_t)bb * (T_STEPS * 8) + half * 4);
        *reinterpret_cast<float4*>(&xbuf[0][b][half * 4]) = v;
    }
    __syncthreads();

    int p = 0;   // h0 buffer parity (h0buf[p] holds h0(it-1) at slot it)
    int q = 0;   // h1 buffer parity (h1buf[q] holds h1(it-2) at slot it)

    for (int it = 0; it <= T_STEPS; ++it) {
        float pacc[NB];                 // G2 partial, carried across the barrier

        if (g == 0) {
            if (it < T_STEPS) {
                ull acc[NB];
#pragma unroll
                for (int b = 0; b < NB; ++b) acc[b] = pack2(bias0, 0.0f);
                const float* hrow = &h0buf[p][0][0];
#pragma unroll
                for (int i = 0; i < 16; ++i) {
                    const ull w0 = w[2 * i], w1 = w[2 * i + 1];
#pragma unroll
                    for (int b = 0; b < NB; ++b) {
                        ulonglong2 hv = *reinterpret_cast<const ulonglong2*>(hrow + b * 64 + i * 4);
                        acc[b] = ffma2(w0, hv.x, acc[b]);
                        acc[b] = ffma2(w1, hv.y, acc[b]);
                    }
                }
                const float* xrow = &xbuf[it & 1][0][0];
#pragma unroll
                for (int b = 0; b < NB; ++b) {
                    ulonglong2 xv0 = *reinterpret_cast<const ulonglong2*>(xrow + b * 8);
                    ulonglong2 xv1 = *reinterpret_cast<const ulonglong2*>(xrow + b * 8 + 4);
                    acc[b] = ffma2(wx[0], xv0.x, acc[b]);
                    acc[b] = ffma2(wx[1], xv0.y, acc[b]);
                    acc[b] = ffma2(wx[2], xv1.x, acc[b]);
                    acc[b] = ffma2(wx[3], xv1.y, acc[b]);
                    h0buf[p ^ 1][b][j] = tanh_fast(hsum2(acc[b]));
                }
            }
        } else if (g == 1) {
            if (it >= 1) {
                // cbuf(it) = W_ih1 . h0(it-1)
                ull acc[NB];
#pragma unroll
                for (int b = 0; b < NB; ++b) acc[b] = 0ull;
                const float* hrow = &h0buf[p][0][0];
#pragma unroll
                for (int i = 0; i < 16; ++i) {
                    const ull w0 = w[2 * i], w1 = w[2 * i + 1];
#pragma unroll
                    for (int b = 0; b < NB; ++b) {
                        ulonglong2 hv = *reinterpret_cast<const ulonglong2*>(hrow + b * 64 + i * 4);
                        acc[b] = ffma2(w0, hv.x, acc[b]);
                        acc[b] = ffma2(w1, hv.y, acc[b]);
                    }
                }
#pragma unroll
                for (int b = 0; b < NB; ++b) cbuf[it & 1][b][j] = hsum2(acc[b]);
            }
            // prefetch x(it+1) into the other xbuf
            if (it + 1 < T_STEPS) {
                int l = tid - 64;
                if (l < 2 * NB) {
                    int b = l >> 1, half = l & 1;
                    int bb = b0 + b; if (bb > 2047) bb = 2047;
                    float4 v = *reinterpret_cast<const float4*>(
                        x + (size_t)bb * (T_STEPS * 8) + (it + 1) * 8 + half * 4);
                    *reinterpret_cast<float4*>(&xbuf[(it + 1) & 1][b][half * 4]) = v;
                }
            }
        } else {
            if (it >= 1) {
                // pacc = W_hh1 . h1(it-2) + bias1
                ull acc[NB];
#pragma unroll
                for (int b = 0; b < NB; ++b) acc[b] = pack2(bias1, 0.0f);
                const float* hrow = &h1buf[q][0][0];
#pragma unroll
                for (int i = 0; i < 16; ++i) {
                    const ull w0 = w[2 * i], w1 = w[2 * i + 1];
#pragma unroll
                    for (int b = 0; b < NB; ++b) {
                        ulonglong2 hv = *reinterpret_cast<const ulonglong2*>(hrow + b * 64 + i * 4);
                        acc[b] = ffma2(w0, hv.x, acc[b]);
                        acc[b] = ffma2(w1, hv.y, acc[b]);
                    }
                }
#pragma unroll
                for (int b = 0; b < NB; ++b) pacc[b] = hsum2(acc[b]);
            }
        }

        __syncthreads();   // publishes: h0(it) [G0], cbuf(it) [G1], xbuf(it+1) [G1]

        if (g == 2 && it >= 1) {
            // h1(it-1) = tanh(W_ih1 h0(it-1) + W_hh1 h1(it-2) + biases)
#pragma unroll
            for (int b = 0; b < NB; ++b)
                h1buf[q ^ 1][b][j] = tanh_fast(pacc[b] + cbuf[it & 1][b][j]);
            asm volatile("bar.sync 1, 64;" ::: "memory");  // G2-private: order write -> next read
        }

        if (it < T_STEPS) p ^= 1;
        if (it >= 1)      q ^= 1;
    }

    __syncthreads();

    // final FC on h1(T-1)
    if (tid < NB && b0 + tid < 2048) {
        float s = fcb[0];
        const float* hrow = &h1buf[q][tid][0];
#pragma unroll 16
        for (int k = 0; k < 64; ++k) s += hrow[k] * fcw[k];
        out[b0 + tid] = s;
    }
}

extern "C" void kernel_launch(void* const* d_in, const int* in_sizes, int n_in,
                              void* d_out, int out_size)
{
    const float* x    = (const float*)d_in[0];
    const float* Wih0 = (const float*)d_in[1];
    const float* Whh0 = (const float*)d_in[2];
    const float* bih0 = (const float*)d_in[3];
    const float* bhh0 = (const float*)d_in[4];
    const float* Wih1 = (const float*)d_in[5];
    const float* Whh1 = (const float*)d_in[6];
    const float* bih1 = (const float*)d_in[7];
    const float* bhh1 = (const float*)d_in[8];
    const float* fcw  = (const float*)d_in[9];
    const float* fcb  = (const float*)d_in[10];
    float* out = (float*)d_out;

    rnn_ws_kernel<<<NBLK, NTHREADS>>>(
        x, Wih0, Whh0, bih0, bhh0, Wih1, Whh1, bih1, bhh1, fcw, fcb, out);
}

// round 9
// speedup vs baseline: 1.9410x; 1.0710x over previous
#include <cuda_runtime.h>
#include <cuda_bf16.h>

#define T_STEPS 512
#define NB 14                         // batches per block
#define NBLK ((2048 + NB - 1) / NB)   // 147 blocks -> one wave, 1 CTA/SM
#define NTHREADS 256                  // warps 0-3: role A, warps 4-7: role B

typedef unsigned long long ull;

__device__ __forceinline__ ull ffma2(ull a, ull b, ull c) {
    ull d;
    asm("fma.rn.f32x2 %0, %1, %2, %3;" : "=l"(d) : "l"(a), "l"(b), "l"(c));
    return d;
}
__device__ __forceinline__ float hsum2(ull v) {
    float lo, hi;
    asm("mov.b64 {%0, %1}, %2;" : "=f"(lo), "=f"(hi) : "l"(v));
    return lo + hi;
}
__device__ __forceinline__ ull pack2(float lo, float hi) {
    ull d;
    asm("mov.b64 %0, {%1, %2};" : "=l"(d) : "f"(lo), "f"(hi));
    return d;
}
// branch-free tanh: 1 - 2/(exp(2s)+1) via ex2/rcp approx (abs err ~1e-7)
__device__ __forceinline__ float tanh_fast(float s) {
    float e;
    asm("ex2.approx.f32 %0, %1;" : "=f"(e) : "f"(s * 2.8853900817779268f));
    float r;
    asm("rcp.approx.f32 %0, %1;" : "=f"(r) : "f"(e + 1.0f));
    return __fmaf_rn(-2.0f, r, 1.0f);
}

__global__ __launch_bounds__(NTHREADS, 1)
void rnn_ws_kernel(const float* __restrict__ x,
                   const float* __restrict__ Wih0,
                   const float* __restrict__ Whh0,
                   const float* __restrict__ bih0,
                   const float* __restrict__ bhh0,
                   const float* __restrict__ Wih1,
                   const float* __restrict__ Whh1,
                   const float* __restrict__ bih1,
                   const float* __restrict__ bhh1,
                   const float* __restrict__ fcw,
                   const float* __restrict__ fcb,
                   float* __restrict__ out)
{
    __shared__ __align__(16) float h0buf[2][NB][64];
    __shared__ __align__(16) float h1buf[2][NB][64];
    __shared__ __align__(16) float cbuf[2][NB][64];   // W_ih1 . h0 partial (double-buffered)
    __shared__ __align__(16) float xbuf[2][NB][8];    // x slice (double-buffered)

    const int tid = threadIdx.x;
    const int j   = tid & 63;            // output unit
    const int g   = tid >> 6;            // 0,1: role A halves; 2,3: role B halves
    const bool isA = (g < 2);
    const int bo  = (g & 1) * 7;         // this half's first batch within the block (7 batches)
    const int b0  = blockIdx.x * NB;

    // ---- W rows in registers, packed f32x2 ----
    // A threads: Whh0 row + Wih1 row + Wih0 row.  B threads: Whh1 row.
    ull wa[32];          // A: Whh0[j][.], B: Whh1[j][.]
    ull wc[32];          // A only: Wih1[j][.]
    ull wx[4] = {0, 0, 0, 0};
    float bias0 = 0.f, bias1 = 0.f;

    {
        const float* s0 = isA ? (Whh0 + j * 64) : (Whh1 + j * 64);
#pragma unroll
        for (int i = 0; i < 16; ++i) {
            ulonglong2 v = *reinterpret_cast<const ulonglong2*>(s0 + i * 4);
            wa[2 * i] = v.x; wa[2 * i + 1] = v.y;
        }
    }
    if (isA) {
        const float* s1 = Wih1 + j * 64;
#pragma unroll
        for (int i = 0; i < 16; ++i) {
            ulonglong2 v = *reinterpret_cast<const ulonglong2*>(s1 + i * 4);
            wc[2 * i] = v.x; wc[2 * i + 1] = v.y;
        }
        ulonglong2 v0 = *reinterpret_cast<const ulonglong2*>(Wih0 + j * 8);
        ulonglong2 v1 = *reinterpret_cast<const ulonglong2*>(Wih0 + j * 8 + 4);
        wx[0] = v0.x; wx[1] = v0.y; wx[2] = v1.x; wx[3] = v1.y;
        bias0 = bih0[j] + bhh0[j];
    } else {
        bias1 = bih1[j] + bhh1[j];
    }

    // zero initial states
    for (int idx = tid; idx < NB * 64; idx += NTHREADS) {
        (&h0buf[0][0][0])[idx] = 0.0f;
        (&h1buf[0][0][0])[idx] = 0.0f;
    }
    // preload x(0)
    if (tid < 2 * NB) {
        int b = tid >> 1, half = tid & 1;
        int bb = b0 + b; if (bb > 2047) bb = 2047;
        float4 v = *reinterpret_cast<const float4*>(x + (size_t)bb * (T_STEPS * 8) + half * 4);
        *reinterpret_cast<float4*>(&xbuf[0][b][half * 4]) = v;
    }
    __syncthreads();

    int p = 0;   // h0buf[p] holds h0(it-1) at slot it
    int q = 0;   // h1buf[q] holds h1(it-2) at slot it

    for (int it = 0; it <= T_STEPS; ++it) {
        float pacc[7];

        if (isA) {
            // One pass over h0(it-1): acc0 -> h0(it), acc1 -> cbuf for h1(it-1)
            ull acc0[7], acc1[7];
#pragma unroll
            for (int b = 0; b < 7; ++b) { acc0[b] = pack2(bias0, 0.0f); acc1[b] = 0ull; }
            const float* hrow = &h0buf[p][bo][0];
#pragma unroll
            for (int i = 0; i < 16; ++i) {
                const ull w0a = wa[2 * i], w1a = wa[2 * i + 1];
                const ull w0c = wc[2 * i], w1c = wc[2 * i + 1];
#pragma unroll
                for (int b = 0; b < 7; ++b) {
                    ulonglong2 hv = *reinterpret_cast<const ulonglong2*>(hrow + b * 64 + i * 4);
                    acc0[b] = ffma2(w0a, hv.x, acc0[b]);
                    acc0[b] = ffma2(w1a, hv.y, acc0[b]);
                    acc1[b] = ffma2(w0c, hv.x, acc1[b]);
                    acc1[b] = ffma2(w1c, hv.y, acc1[b]);
                }
            }
            // cbuf(it) = Wih1 . h0(it-1)
#pragma unroll
            for (int b = 0; b < 7; ++b) cbuf[it & 1][bo + b][j] = hsum2(acc1[b]);
            // h0(it) = tanh(Whh0 h0(it-1) + x(it) Wih0 + b0)
            if (it < T_STEPS) {
                const float* xrow = &xbuf[it & 1][bo][0];
#pragma unroll
                for (int b = 0; b < 7; ++b) {
                    ulonglong2 xv0 = *reinterpret_cast<const ulonglong2*>(xrow + b * 8);
                    ulonglong2 xv1 = *reinterpret_cast<const ulonglong2*>(xrow + b * 8 + 4);
                    acc0[b] = ffma2(wx[0], xv0.x, acc0[b]);
                    acc0[b] = ffma2(wx[1], xv0.y, acc0[b]);
                    acc0[b] = ffma2(wx[2], xv1.x, acc0[b]);
                    acc0[b] = ffma2(wx[3], xv1.y, acc0[b]);
                    h0buf[p ^ 1][bo + b][j] = tanh_fast(hsum2(acc0[b]));
                }
            }
        } else {
            if (it >= 1) {
                // pacc = Whh1 . h1(it-2) + bias1
                ull acc[7];
#pragma unroll
                for (int b = 0; b < 7; ++b) acc[b] = pack2(bias1, 0.0f);
                const float* hrow = &h1buf[q][bo][0];
#pragma unroll
                for (int i = 0; i < 16; ++i) {
                    const ull w0 = wa[2 * i], w1 = wa[2 * i + 1];
#pragma unroll
                    for (int b = 0; b < 7; ++b) {
                        ulonglong2 hv = *reinterpret_cast<const ulonglong2*>(hrow + b * 64 + i * 4);
                        acc[b] = ffma2(w0, hv.x, acc[b]);
                        acc[b] = ffma2(w1, hv.y, acc[b]);
                    }
                }
#pragma unroll
                for (int b = 0; b < 7; ++b) pacc[b] = hsum2(acc[b]);
            }
            // prefetch x(it+1)
            if (it + 1 < T_STEPS) {
                int l = tid - 128;
                if (l < 2 * NB) {
                    int b = l >> 1, half = l & 1;
                    int bb = b0 + b; if (bb > 2047) bb = 2047;
                    float4 v = *reinterpret_cast<const float4*>(
                        x + (size_t)bb * (T_STEPS * 8) + (it + 1) * 8 + half * 4);
                    *reinterpret_cast<float4*>(&xbuf[(it + 1) & 1][b][half * 4]) = v;
                }
            }
        }

        __syncthreads();   // publishes h0(it), cbuf(it), xbuf(it+1)

        if (!isA && it >= 1) {
            // h1(it-1) = tanh(Wih1 h0(it-1) + Whh1 h1(it-2) + biases)
#pragma unroll
            for (int b = 0; b < 7; ++b)
                h1buf[q ^ 1][bo + b][j] = tanh_fast(pacc[b] + cbuf[it & 1][bo + b][j]);
            // pair-private ordering: h1 writes -> next slot's h1 reads (64 threads each)
            if (g == 2) asm volatile("bar.sync 1, 64;" ::: "memory");
            else        asm volatile("bar.sync 2, 64;" ::: "memory");
        }

        if (it < T_STEPS) p ^= 1;
        if (it >= 1)      q ^= 1;
    }

    __syncthreads();

    // final FC on h1(T-1)
    if (tid < NB && b0 + tid < 2048) {
        float s = fcb[0];
        const float* hrow = &h1buf[q][tid][0];
#pragma unroll 16
        for (int k = 0; k < 64; ++k) s += hrow[k] * fcw[k];
        out[b0 + tid] = s;
    }
}

extern "C" void kernel_launch(void* const* d_in, const int* in_sizes, int n_in,
                              void* d_out, int out_size)
{
    const float* x    = (const float*)d_in[0];
    const float* Wih0 = (const float*)d_in[1];
    const float* Whh0 = (const float*)d_in[2];
    const float* bih0 = (const float*)d_in[3];
    const float* bhh0 = (const float*)d_in[4];
    const float* Wih1 = (const float*)d_in[5];
    const float* Whh1 = (const float*)d_in[6];
    const float* bih1 = (const float*)d_in[7];
    const float* bhh1 = (const float*)d_in[8];
    const float* fcw  = (const float*)d_in[9];
    const float* fcb  = (const float*)d_in[10];
    float* out = (float*)d_out;

    rnn_ws_kernel<<<NBLK, NTHREADS>>>(
        x, Wih0, Whh0, bih0, bhh0, Wih1, Whh1, bih1, bhh1, fcw, fcb, out);
}